// round 17
// baseline (speedup 1.0000x reference)
#include <cuda_runtime.h>
#include <math.h>

#define N_NODES 50000
#define N_EDGES 800000
#define C 64
#define OUTC 16
#define NG 196          // ceil(N_NODES/256)
#define E4G 782         // ceil(N_EDGES/4/256)
#define LTG 782         // ceil(N_NODES/64)
#define COLBUF 1280     // >= sum of 64 node degrees w.p. 1-1e-15 (Poisson(1024), 8 sigma)
#define BN_EPS 1e-5f
typedef unsigned long long ull;

// ---- packed f32x2 helpers (sm_103a FFMA2) ----
#define FMA2(d, a, b, c) \
    asm("fma.rn.f32x2 %0, %1, %2, %3;" : "=l"(d) : "l"(a), "l"(b), "l"(c))
#define PACKF2(out, lo, hi) \
    asm("mov.b64 %0, {%1, %2};" : "=l"(out) : "r"(__float_as_uint(lo)), "r"(__float_as_uint(hi)))
#define UNPACKF2(lo, hi, in) \
    { unsigned int _l, _h; asm("mov.b64 {%0, %1}, %2;" : "=r"(_l), "=r"(_h) : "l"(in)); \
      lo = __uint_as_float(_l); hi = __uint_as_float(_h); }

// ---------------- device scratch ----------------
__device__ __align__(16) float g_bufB[N_NODES * C];   // layer-1 pre-BN output
__device__ __align__(16) float g_bufD[N_NODES * C];   // layer-2 pre-BN output
__device__ float g_partS[LTG * C];
__device__ float g_partQ[LTG * C];
__device__ __align__(16) float g_bnp[2 * C];          // [scale | shift]
__device__ int   g_deg[N_NODES];
__device__ int   g_start[N_NODES];
__device__ int   g_end[N_NODES];
__device__ int   g_cursor[N_NODES];
__device__ int   g_col[N_EDGES];
__device__ int   g_total;
__device__ int   g_done;

// ---------------- CSR build (3 kernels) ----------------
__global__ void hist_kernel(const int* __restrict__ ei) {
    if (blockIdx.x == 0 && threadIdx.x == 0) { g_total = 0; g_done = 0; }
    int e4 = blockIdx.x * 256 + threadIdx.x;
    if (e4 < N_EDGES / 4) {
        int4 d = ((const int4*)(ei + N_EDGES))[e4];
        atomicAdd(&g_deg[d.x], 1);
        atomicAdd(&g_deg[d.y], 1);
        atomicAdd(&g_deg[d.z], 1);
        atomicAdd(&g_deg[d.w], 1);
    }
}

// Range allocation: ORDERED scan within each 256-node chunk (so any aligned
// 64-node tile owns a contiguous ascending col slice), chunk bases unordered
// via one atomic (min is placement-invariant).
__global__ void offsets_kernel() {
    __shared__ int wtot[8];
    __shared__ int blockbase;
    int t = threadIdx.x, i = blockIdx.x * 256 + t;
    int lane = t & 31, w = t >> 5;
    int d = (i < N_NODES) ? g_deg[i] : 0;
    int sc = d;
#pragma unroll
    for (int off = 1; off < 32; off <<= 1) {
        int n = __shfl_up_sync(0xffffffffu, sc, off);
        if (lane >= off) sc += n;
    }
    if (lane == 31) wtot[w] = sc;
    __syncthreads();
    if (w == 0) {
        int v = (lane < 8) ? wtot[lane] : 0;
#pragma unroll
        for (int off = 1; off < 8; off <<= 1) {
            int n = __shfl_up_sync(0xffffffffu, v, off);
            if (lane >= off) v += n;
        }
        if (lane < 8) wtot[lane] = v;
        if (lane == 7) blockbase = atomicAdd(&g_total, v);
    }
    __syncthreads();
    int beg = blockbase + ((w == 0) ? 0 : wtot[w - 1]) + sc - d;
    if (i < N_NODES) {
        g_start[i]  = beg;
        g_end[i]    = beg + d;
        g_cursor[i] = beg;
        g_deg[i]    = 0;     // ready for next graph replay
    }
}

__global__ void scatter_kernel(const int* __restrict__ ei) {
    int e4 = blockIdx.x * 256 + threadIdx.x;
    if (e4 < N_EDGES / 4) {
        int4 s = ((const int4*)ei)[e4];
        int4 d = ((const int4*)(ei + N_EDGES))[e4];
        g_col[atomicAdd(&g_cursor[d.x], 1)] = s.x;
        g_col[atomicAdd(&g_cursor[d.y], 1)] = s.y;
        g_col[atomicAdd(&g_cursor[d.z], 1)] = s.z;
        g_col[atomicAdd(&g_cursor[d.w], 1)] = s.w;
    }
}

#define FMIN4(a, v) \
    { (a).x = fminf((a).x, (v).x); (a).y = fminf((a).y, (v).y); \
      (a).z = fminf((a).z, (v).z); (a).w = fminf((a).w, (v).w); }

// Gather inner loops: cols from smem (fast path) or global (overflow fallback).
#define GATHER_LOOP(COLEXPR)                                                        \
    for (int k = 0; k < maxd; k++) {                                                \
        if (k < degs[0]) { int c = (COLEXPR(0)); float4 v = src4[c * 16 + c4]; FMIN4(a0, v); } \
        if (k < degs[1]) { int c = (COLEXPR(1)); float4 v = src4[c * 16 + c4]; FMIN4(a1, v); } \
        if (k < degs[2]) { int c = (COLEXPR(2)); float4 v = src4[c * 16 + c4]; FMIN4(a2, v); } \
        if (k < degs[3]) { int c = (COLEXPR(3)); float4 v = src4[c * 16 + c4]; FMIN4(a3, v); } \
    }
#define COL_SMEM(s) scol[offs[s] + k]
#define COL_GMEM(s) g_col[offs[s] + k]

// ---------------- interleaved 4-node gather-min into sX --------------------
// Thread (c4 = tid&15 channel quad, sub = tid>>4) handles nodes base+sub+16s.
// Col indices come from the block-staged smem slice (29-cyc broadcast LDS)
// so feature loads have no L2-latency address chain. Predicates uniform per
// 16-lane group (no divergence).
__device__ __forceinline__ void gather4(const float4* __restrict__ src4,
                                        const int* __restrict__ scol, bool fit,
                                        int S, int base, int c4, int sub,
                                        float* __restrict__ sX, bool bn) {
    int offs[4], degs[4];
#pragma unroll
    for (int s = 0; s < 4; s++) {
        int node = base + s * 16 + sub;
        int b = 0, d = 0;
        if (node < N_NODES) { b = g_start[node]; d = g_end[node] - b; }
        offs[s] = fit ? (b - S) : b;
        degs[s] = d;
    }
    int maxd = max(max(degs[0], degs[1]), max(degs[2], degs[3]));
    const float INF = __int_as_float(0x7f800000);
    float4 a0 = {INF, INF, INF, INF}, a1 = a0, a2 = a0, a3 = a0;

    if (fit) { GATHER_LOOP(COL_SMEM) } else { GATHER_LOOP(COL_GMEM) }

    float4 sc, sh;
    if (bn) {
        sc = *(const float4*)&g_bnp[c4 * 4];
        sh = *(const float4*)&g_bnp[64 + c4 * 4];
    }
    float4 accs[4] = {a0, a1, a2, a3};
#pragma unroll
    for (int s = 0; s < 4; s++) {
        float4 m = accs[s];
        if (degs[s] == 0) m = make_float4(0.f, 0.f, 0.f, 0.f);
        else if (bn) {
            m.x = fmaxf(m.x * sc.x + sh.x, 0.f);
            m.y = fmaxf(m.y * sc.y + sh.y, 0.f);
            m.z = fmaxf(m.z * sc.z + sh.z, 0.f);
            m.w = fmaxf(m.w * sc.w + sh.w, 0.f);
        }
        int o = (s * 16 + sub) * 65 + 4 * c4;
        sX[o] = m.x; sX[o + 1] = m.y; sX[o + 2] = m.z; sX[o + 3] = m.w;
    }
}

// ---------------- fused layer: gather-min + dual-GEMM 64->64 + BN stats -----
#define MMA64() \
    _Pragma("unroll 4") \
    for (int ci = 0; ci < 64; ci++) { \
        ull bw0 = *(const ull*)&sW[ci * 64 + 2 * cg]; \
        ull bw1 = *(const ull*)&sW[ci * 64 + 2 * cg + 32]; \
        float x0 = sX[slot * 65 + ci]; \
        float x1 = sX[(slot + 16) * 65 + ci]; \
        float x2 = sX[(slot + 32) * 65 + ci]; \
        float x3 = sX[(slot + 48) * 65 + ci]; \
        ull a0, a1, a2, a3; \
        PACKF2(a0, x0, x0); PACKF2(a1, x1, x1); PACKF2(a2, x2, x2); PACKF2(a3, x3, x3); \
        FMA2(acc[0][0], a0, bw0, acc[0][0]); FMA2(acc[1][0], a0, bw1, acc[1][0]); \
        FMA2(acc[0][1], a1, bw0, acc[0][1]); FMA2(acc[1][1], a1, bw1, acc[1][1]); \
        FMA2(acc[0][2], a2, bw0, acc[0][2]); FMA2(acc[1][2], a2, bw1, acc[1][2]); \
        FMA2(acc[0][3], a3, bw0, acc[0][3]); FMA2(acc[1][3], a3, bw1, acc[1][3]); \
    }

__global__ void __launch_bounds__(256, 6)
layer64_kernel(const float* __restrict__ xin, int use_bn,
               const float* __restrict__ Wl,
               const float* __restrict__ Wr,
               const float* __restrict__ bias,
               const float* __restrict__ gam,
               const float* __restrict__ bet) {
    __shared__ __align__(16) float sW[64 * 64];
    __shared__ __align__(16) float sX[64 * 65];
    __shared__ int  sCol[COLBUF];
    __shared__ bool amLast;
    float* sRS = sX;              // aliased: sX dead after last MMA
    float* sRQ = sX + 1024;

    int tid = threadIdx.x;
    int base = blockIdx.x * 64;
    const float* hsrc = use_bn ? (const float*)g_bufB : xin;
    float* dst = use_bn ? g_bufD : g_bufB;      // double buffer: never in-place
    const float4* src4 = (const float4*)hsrc;

    // Wl -> smem (float4)
    for (int q = tid; q < 1024; q += 256)
        ((float4*)sW)[q] = ((const float4*)Wl)[q];

    // ---- stage this tile's contiguous col slice into smem ----
    int S = g_start[base];
    int lastn = min(base + 63, N_NODES - 1);
    int ncol = g_end[lastn] - S;
    bool fit = (ncol <= COLBUF);
    if (fit)
        for (int q = tid; q < ncol; q += 256) sCol[q] = g_col[S + q];
    __syncthreads();

    // ---- gather-min phase ----
    int c4 = tid & 15, sub = tid >> 4;
    gather4(src4, sCol, fit, S, base, c4, sub, sX, use_bn != 0);
    __syncthreads();

    // ---- GEMM pass 1: Wl x agg ----
    int cg = c4, slot = sub;
    ull acc[2][4];
    {
        float2 bp0 = *(const float2*)&bias[2 * cg];
        float2 bp1 = *(const float2*)&bias[2 * cg + 32];
        ull b0, b1;
        PACKF2(b0, bp0.x, bp0.y);
        PACKF2(b1, bp1.x, bp1.y);
#pragma unroll
        for (int j = 0; j < 4; j++) { acc[0][j] = b0; acc[1][j] = b1; }
    }
    MMA64();
    __syncthreads();

    // ---- GEMM pass 2: Wr x h (BN+ReLU fused on load; float4) ----
    for (int q = tid; q < 1024; q += 256)
        ((float4*)sW)[q] = ((const float4*)Wr)[q];
    for (int q = tid; q < 1024; q += 256) {
        int nd = q >> 4, cq = q & 15, gn = base + nd;
        float4 v = make_float4(0.f, 0.f, 0.f, 0.f);
        if (gn < N_NODES) {
            v = src4[gn * 16 + cq];
            if (use_bn) {
                float4 bsc = *(const float4*)&g_bnp[cq * 4];
                float4 bsh = *(const float4*)&g_bnp[64 + cq * 4];
                v.x = fmaxf(v.x * bsc.x + bsh.x, 0.f);
                v.y = fmaxf(v.y * bsc.y + bsh.y, 0.f);
                v.z = fmaxf(v.z * bsc.z + bsh.z, 0.f);
                v.w = fmaxf(v.w * bsc.w + bsh.w, 0.f);
            }
        }
        int o = nd * 65 + 4 * cq;
        sX[o] = v.x; sX[o + 1] = v.y; sX[o + 2] = v.z; sX[o + 3] = v.w;
    }
    __syncthreads();
    MMA64();
    __syncthreads();   // sX reads done; safe to alias sRS/sRQ

    // ---- epilogue: store output pairs + BN partials ----
#pragma unroll
    for (int p = 0; p < 2; p++) {
        int co0 = 2 * cg + 32 * p;
        float s1l = 0.f, s2l = 0.f, s1h = 0.f, s2h = 0.f;
#pragma unroll
        for (int j = 0; j < 4; j++) {
            int gn = base + slot + 16 * j;
            float lo, hi;
            UNPACKF2(lo, hi, acc[p][j]);
            if (gn < N_NODES) {
                *(float2*)&dst[gn * C + co0] = make_float2(lo, hi);
                s1l += lo; s2l += lo * lo;
                s1h += hi; s2h += hi * hi;
            }
        }
        sRS[co0 * 16 + slot] = s1l;
        sRQ[co0 * 16 + slot] = s2l;
        sRS[(co0 + 1) * 16 + slot] = s1h;
        sRQ[(co0 + 1) * 16 + slot] = s2h;
    }
    __syncthreads();
    if (tid < 64) {
        float t1 = 0.0f, t2 = 0.0f;
#pragma unroll
        for (int s = 0; s < 16; s++) {
            t1 += sRS[tid * 16 + s];
            t2 += sRQ[tid * 16 + s];
        }
        g_partS[blockIdx.x * 64 + tid] = t1;
        g_partQ[blockIdx.x * 64 + tid] = t2;
    }
    __threadfence();
    __syncthreads();

    // ---- last block computes BN scale/shift (fixed-order, deterministic) ----
    if (tid == 0) amLast = (atomicAdd(&g_done, 1) == LTG - 1);
    __syncthreads();
    if (amLast) {
        __threadfence();
        int c = tid & 63, part = tid >> 6;
        float s = 0.0f, q = 0.0f;
        for (int i = part; i < LTG; i += 4) {
            s += g_partS[i * 64 + c];
            q += g_partQ[i * 64 + c];
        }
        sRS[tid] = s;
        sRQ[tid] = q;
        __syncthreads();
        if (tid < 64) {
            float S2 = sRS[tid] + sRS[tid + 64] + sRS[tid + 128] + sRS[tid + 192];
            float Q2 = sRQ[tid] + sRQ[tid + 64] + sRQ[tid + 128] + sRQ[tid + 192];
            float inv = 1.0f / (float)N_NODES;
            float mu = S2 * inv;
            float var = Q2 * inv - mu * mu;
            float scale = gam[tid] * rsqrtf(var + BN_EPS);
            g_bnp[tid] = scale;
            g_bnp[64 + tid] = bet[tid] - mu * scale;
        }
        if (tid == 0) g_done = 0;   // ready for next layer / replay
    }
}

// ---------------- fused layer 3: gather-min + dual-GEMM 64->16 + log_softmax
__global__ void __launch_bounds__(256, 5)
layer16_kernel(const float* __restrict__ Wl,
               const float* __restrict__ Wr,
               const float* __restrict__ b,
               float* __restrict__ out) {
    __shared__ float sWl[64 * 16], sWr[64 * 16];
    __shared__ __align__(16) float sA[64 * 65];
    __shared__ __align__(16) float sH[64 * 65];
    __shared__ int sCol[COLBUF];

    int tid = threadIdx.x;
    int base = blockIdx.x * 64;
    const float4* src4 = (const float4*)g_bufD;   // layer-2 output buffer

    for (int q = tid; q < 1024; q += 256) { sWl[q] = Wl[q]; sWr[q] = Wr[q]; }

    // stage col slice
    int S = g_start[base];
    int lastn = min(base + 63, N_NODES - 1);
    int ncol = g_end[lastn] - S;
    bool fit = (ncol <= COLBUF);
    if (fit)
        for (int q = tid; q < ncol; q += 256) sCol[q] = g_col[S + q];
    __syncthreads();

    // gather-min of h2 rows (bn2+relu post-min, monotone) into sA
    int c4 = tid & 15, sub = tid >> 4;
    gather4(src4, sCol, fit, S, base, c4, sub, sA, true);

    // h2 rows (contiguous, float4) with bn2+relu into sH
    for (int q = tid; q < 1024; q += 256) {
        int nd = q >> 4, cq = q & 15, gn = base + nd;
        float4 v = make_float4(0.f, 0.f, 0.f, 0.f);
        if (gn < N_NODES) {
            v = src4[gn * 16 + cq];
            float4 bsc = *(const float4*)&g_bnp[cq * 4];
            float4 bsh = *(const float4*)&g_bnp[64 + cq * 4];
            v.x = fmaxf(v.x * bsc.x + bsh.x, 0.f);
            v.y = fmaxf(v.y * bsc.y + bsh.y, 0.f);
            v.z = fmaxf(v.z * bsc.z + bsh.z, 0.f);
            v.w = fmaxf(v.w * bsc.w + bsh.w, 0.f);
        }
        int o = nd * 65 + 4 * cq;
        sH[o] = v.x; sH[o + 1] = v.y; sH[o + 2] = v.z; sH[o + 3] = v.w;
    }
    __syncthreads();

    int c_out = tid & 15, nslot = tid >> 4;
    float acc[4];
    float bb = b[c_out];
#pragma unroll
    for (int j = 0; j < 4; j++) acc[j] = bb;

#pragma unroll 8
    for (int ci = 0; ci < 64; ci++) {
        float wl = sWl[ci * 16 + c_out];
        float wr = sWr[ci * 16 + c_out];
#pragma unroll
        for (int j = 0; j < 4; j++) {
            int nd = nslot + 16 * j;
            acc[j] += sA[nd * 65 + ci] * wl + sH[nd * 65 + ci] * wr;
        }
    }

    // log_softmax: 16 channels of a node live in 16 consecutive lanes.
#pragma unroll
    for (int j = 0; j < 4; j++) {
        int gn = base + nslot + 16 * j;
        float v = acc[j];
        float m = v;
#pragma unroll
        for (int off = 8; off; off >>= 1)
            m = fmaxf(m, __shfl_xor_sync(0xffffffffu, m, off));
        float e = expf(v - m);
        float s = e;
#pragma unroll
        for (int off = 8; off; off >>= 1)
            s += __shfl_xor_sync(0xffffffffu, s, off);
        if (gn < N_NODES) out[gn * OUTC + c_out] = v - m - logf(s);
    }
}

// ---------------- launch: 6 kernel launches ----------------
extern "C" void kernel_launch(void* const* d_in, const int* in_sizes, int n_in,
                              void* d_out, int out_size) {
    const float* x   = (const float*)d_in[0];
    const int*   ei  = (const int*)d_in[1];   // int32 (JAX x64 disabled)
    const float* W1l = (const float*)d_in[2];
    const float* b1  = (const float*)d_in[3];
    const float* W1r = (const float*)d_in[4];
    const float* g1  = (const float*)d_in[5];
    const float* be1 = (const float*)d_in[6];
    const float* W2l = (const float*)d_in[7];
    const float* b2  = (const float*)d_in[8];
    const float* W2r = (const float*)d_in[9];
    const float* g2  = (const float*)d_in[10];
    const float* be2 = (const float*)d_in[11];
    const float* W3l = (const float*)d_in[12];
    const float* b3  = (const float*)d_in[13];
    const float* W3r = (const float*)d_in[14];
    float* out = (float*)d_out;

    hist_kernel<<<E4G, 256>>>(ei);
    offsets_kernel<<<NG, 256>>>();
    scatter_kernel<<<E4G, 256>>>(ei);

    layer64_kernel<<<LTG, 256>>>(x, 0, W1l, W1r, b1, g1, be1);
    layer64_kernel<<<LTG, 256>>>(x, 1, W2l, W2r, b2, g2, be2);
    layer16_kernel<<<LTG, 256>>>(W3l, W3r, b3, out);
}